// round 1
// baseline (speedup 1.0000x reference)
#include <cuda_runtime.h>
#include <math.h>

#define B_ 2
#define L_ 512
#define C_ 256
#define H_ 8
#define D_ 32
#define SCALE_ 0.17677669529663687f   // 1/sqrt(32)

// ------------------------- scratch (device globals, no allocs) -------------
__device__ float g_q[B_*H_*L_*D_];          // 1 MB
__device__ float g_k[B_*H_*L_*D_];          // 1 MB
__device__ float g_v[B_*H_*L_*D_];          // 1 MB
__device__ float g_rel[B_*H_*L_*L_];        // 16 MB, layout [b][h][l][m]
__device__ float g_att[B_*L_*C_];           // 1 MB, layout [b][l][h*32+d]

// ===========================================================================
// GEMM: out[m][n] = sum_k A[m][k] * W[n][k]   (A: [1024][256], W: [N][256])
// mode 0: N=768, scatter into g_q/g_k/g_v as [b][h][l][d]
// mode 1: N=256, A = g_att, out[m*256+n] = acc + bias[n]
// Tiles 64x64, K-chunk 32, 256 threads, 4x4 micro-tile.
// ===========================================================================
__global__ __launch_bounds__(256) void gemm_kernel(
    const float* __restrict__ A, const float* __restrict__ W,
    const float* __restrict__ bias, float* __restrict__ out, int mode)
{
    __shared__ float As[32][68];
    __shared__ float Ws[32][68];
    const float* Ap = (mode == 0) ? A : g_att;
    int tid  = threadIdx.x;
    int row0 = blockIdx.x * 64;
    int col0 = blockIdx.y * 64;
    int tx = tid & 15, ty = tid >> 4;
    float acc[4][4];
    #pragma unroll
    for (int i = 0; i < 4; i++)
        #pragma unroll
        for (int j = 0; j < 4; j++) acc[i][j] = 0.f;

    for (int kc = 0; kc < 256; kc += 32) {
        #pragma unroll
        for (int i = 0; i < 2; i++) {
            int idx = tid + i * 256;
            int r = idx >> 3, c4 = idx & 7;
            float4 av = *(const float4*)&Ap[(size_t)(row0 + r) * 256 + kc + c4 * 4];
            As[c4*4+0][r] = av.x; As[c4*4+1][r] = av.y;
            As[c4*4+2][r] = av.z; As[c4*4+3][r] = av.w;
            float4 wv = *(const float4*)&W[(size_t)(col0 + r) * 256 + kc + c4 * 4];
            Ws[c4*4+0][r] = wv.x; Ws[c4*4+1][r] = wv.y;
            Ws[c4*4+2][r] = wv.z; Ws[c4*4+3][r] = wv.w;
        }
        __syncthreads();
        #pragma unroll
        for (int kk = 0; kk < 32; kk++) {
            float4 a4 = *(const float4*)&As[kk][ty * 4];
            float4 b4 = *(const float4*)&Ws[kk][tx * 4];
            float a[4] = {a4.x, a4.y, a4.z, a4.w};
            float b[4] = {b4.x, b4.y, b4.z, b4.w};
            #pragma unroll
            for (int i = 0; i < 4; i++)
                #pragma unroll
                for (int j = 0; j < 4; j++) acc[i][j] += a[i] * b[j];
        }
        __syncthreads();
    }

    #pragma unroll
    for (int i = 0; i < 4; i++) {
        int m  = row0 + ty * 4 + i;
        int bb = m >> 9, l = m & 511;
        #pragma unroll
        for (int j = 0; j < 4; j++) {
            int n = col0 + tx * 4 + j;
            if (mode == 0) {
                int s = n >> 8, rem = n & 255, h = rem >> 5, d = rem & 31;
                float* dst = (s == 0) ? g_q : (s == 1) ? g_k : g_v;
                dst[(((size_t)bb * H_ + h) * L_ + l) * D_ + d] = acc[i][j];
            } else {
                out[(size_t)m * 256 + n] = acc[i][j] + bias[n];
            }
        }
    }
}

// ===========================================================================
// rel bias: rel[b,h,l,m] = LN_h( gelu( rp[b,l,m,:] @ w_rel[h,:] + b_rel[h] ) )
// One thread per (b,l,m)-row; 256 rows per block; rp staged in smem in
// c-chunks of 32 with 36-float row stride (conflict-free LDS.128);
// weights read as warp-uniform smem broadcasts.  This is the hot kernel.
// ===========================================================================
__global__ __launch_bounds__(256) void rel_kernel(
    const float* __restrict__ rp, const float* __restrict__ w_rel,
    const float* __restrict__ b_rel, const float* __restrict__ ln_g,
    const float* __restrict__ ln_b)
{
    __shared__ float tile[256 * 36];   // 36 KB staged rp chunk
    __shared__ float ws[256 * 8];      // w_rel transposed: ws[c*8 + h]
    __shared__ float par[24];          // b_rel | gamma | beta
    int tid = threadIdx.x;

    #pragma unroll
    for (int i = 0; i < 8; i++) {
        int idx = tid + i * 256;                       // idx = h*256 + c
        ws[(idx & 255) * 8 + (idx >> 8)] = w_rel[idx];
    }
    if (tid < 8) { par[tid] = b_rel[tid]; par[8 + tid] = ln_g[tid]; par[16 + tid] = ln_b[tid]; }

    float acc[8];
    #pragma unroll
    for (int h = 0; h < 8; h++) acc[h] = 0.f;

    const float* rowp = rp + (size_t)blockIdx.x * (256 * 256);
    __syncthreads();

    for (int ch = 0; ch < 8; ch++) {
        #pragma unroll
        for (int i = 0; i < 8; i++) {
            int idx = tid + i * 256;
            int rr = idx >> 3, c4 = idx & 7;
            float4 v = *(const float4*)&rowp[(size_t)rr * 256 + ch * 32 + c4 * 4];
            *(float4*)&tile[rr * 36 + c4 * 4] = v;
        }
        __syncthreads();
        const float* trow = &tile[tid * 36];
        #pragma unroll
        for (int c = 0; c < 32; c += 4) {
            float4 r4 = *(const float4*)&trow[c];
            float rv[4] = {r4.x, r4.y, r4.z, r4.w};
            #pragma unroll
            for (int u = 0; u < 4; u++) {
                const float4 w0 = *(const float4*)&ws[(ch * 32 + c + u) * 8];
                const float4 w1 = *(const float4*)&ws[(ch * 32 + c + u) * 8 + 4];
                acc[0] += rv[u] * w0.x; acc[1] += rv[u] * w0.y;
                acc[2] += rv[u] * w0.z; acc[3] += rv[u] * w0.w;
                acc[4] += rv[u] * w1.x; acc[5] += rv[u] * w1.y;
                acc[6] += rv[u] * w1.z; acc[7] += rv[u] * w1.w;
            }
        }
        __syncthreads();
    }

    // epilogue: bias, exact GELU, LayerNorm over H=8, scattered-by-h store
    float gv[8];
    float mu = 0.f;
    #pragma unroll
    for (int h = 0; h < 8; h++) {
        float xv = acc[h] + par[h];
        gv[h] = 0.5f * xv * (1.f + erff(xv * 0.7071067811865475f));
        mu += gv[h];
    }
    mu *= 0.125f;
    float var = 0.f;
    #pragma unroll
    for (int h = 0; h < 8; h++) { float d = gv[h] - mu; var += d * d; }
    var *= 0.125f;
    float rstd = rsqrtf(var + 1e-5f);

    size_t r  = (size_t)blockIdx.x * 256 + tid;   // r = (b*512 + l)*512 + m
    int    m  = (int)(r & 511);
    size_t bl = r >> 9;
    int    bb = (int)(bl >> 9);
    int    l  = (int)(bl & 511);
    size_t base = (((size_t)bb * H_) * L_ + l) * (size_t)L_ + m;
    #pragma unroll
    for (int h = 0; h < 8; h++)
        g_rel[base + (size_t)h * (L_ * L_)] = (gv[h] - mu) * rstd * par[8 + h] + par[16 + h];
}

// ===========================================================================
// attention: per (b, h, 32-l tile). logits in smem (padded rows), k/v rows
// held in registers (2 m-rows per thread), two-pass softmax.
// ===========================================================================
#define LPAD 516
#define ATTN_SMEM_FLOATS (32 * LPAD + 32 * 32 + 32)

__global__ __launch_bounds__(256) void attn_kernel()
{
    extern __shared__ float sm[];
    float* logits = sm;                    // [32][LPAD]
    float* q_s    = sm + 32 * LPAD;        // [32][32]
    float* inv_s  = q_s + 32 * 32;         // [32]
    int tid = threadIdx.x;
    int b = blockIdx.z, h = blockIdx.y, l0 = blockIdx.x * 32;

    const float* qb   = g_q + (((size_t)(b * H_ + h)) * L_ + l0) * D_;
    const float* kb   = g_k + ((size_t)(b * H_ + h)) * L_ * D_;
    const float* vb   = g_v + ((size_t)(b * H_ + h)) * L_ * D_;
    const float* relb = g_rel + (((size_t)(b * H_ + h)) * L_ + l0) * L_;

    { int lq = tid >> 3, d4 = tid & 7;
      *(float4*)&q_s[lq * 32 + d4 * 4] = *(const float4*)&qb[lq * 32 + d4 * 4]; }

    float kr0[32], kr1[32];
    int m0 = tid, m1 = tid + 256;
    #pragma unroll
    for (int j = 0; j < 8; j++) {
        float4 a = *(const float4*)&kb[(size_t)m0 * 32 + j * 4];
        kr0[j*4] = a.x; kr0[j*4+1] = a.y; kr0[j*4+2] = a.z; kr0[j*4+3] = a.w;
        float4 c = *(const float4*)&kb[(size_t)m1 * 32 + j * 4];
        kr1[j*4] = c.x; kr1[j*4+1] = c.y; kr1[j*4+2] = c.z; kr1[j*4+3] = c.w;
    }
    __syncthreads();

    // pass 1: logits = (q.k + rel) * scale
    #pragma unroll 4
    for (int l = 0; l < 32; l++) {
        float s0 = 0.f, s1 = 0.f;
        #pragma unroll
        for (int j = 0; j < 8; j++) {
            float4 qv = *(const float4*)&q_s[l * 32 + j * 4];
            s0 += qv.x*kr0[j*4] + qv.y*kr0[j*4+1] + qv.z*kr0[j*4+2] + qv.w*kr0[j*4+3];
            s1 += qv.x*kr1[j*4] + qv.y*kr1[j*4+1] + qv.z*kr1[j*4+2] + qv.w*kr1[j*4+3];
        }
        logits[l * LPAD + m0] = (s0 + relb[(size_t)l * L_ + m0]) * SCALE_;
        logits[l * LPAD + m1] = (s1 + relb[(size_t)l * L_ + m1]) * SCALE_;
    }
    __syncthreads();

    // softmax: warp per 4 rows
    int lane = tid & 31, wrp = tid >> 5;
    for (int lr = 0; lr < 4; lr++) {
        int l = wrp * 4 + lr;
        float* row = &logits[l * LPAD];
        float vals[16];
        float mx = -1e30f;
        #pragma unroll
        for (int j = 0; j < 16; j++) { vals[j] = row[lane + 32 * j]; mx = fmaxf(mx, vals[j]); }
        #pragma unroll
        for (int o = 16; o > 0; o >>= 1) mx = fmaxf(mx, __shfl_xor_sync(0xffffffff, mx, o));
        float sum = 0.f;
        #pragma unroll
        for (int j = 0; j < 16; j++) {
            float e = expf(vals[j] - mx);
            row[lane + 32 * j] = e;
            sum += e;
        }
        #pragma unroll
        for (int o = 16; o > 0; o >>= 1) sum += __shfl_xor_sync(0xffffffff, sum, o);
        if (lane == 0) inv_s[l] = 1.f / sum;
    }
    __syncthreads();

    // pass 2: out = p @ v  (thread owns (l, 4-d quad))
    int lo = tid >> 3, dq = tid & 7;
    float4 a = make_float4(0.f, 0.f, 0.f, 0.f);
    const float* lrow = &logits[lo * LPAD];
    #pragma unroll 8
    for (int m = 0; m < 512; m++) {
        float  p  = lrow[m];
        float4 vv = *(const float4*)&vb[(size_t)m * 32 + dq * 4];
        a.x += p * vv.x; a.y += p * vv.y; a.z += p * vv.z; a.w += p * vv.w;
    }
    float inv = inv_s[lo];
    a.x *= inv; a.y *= inv; a.z *= inv; a.w *= inv;
    *(float4*)&g_att[((size_t)(b * L_) + l0 + lo) * C_ + h * D_ + dq * 4] = a;
}

// ===========================================================================
extern "C" void kernel_launch(void* const* d_in, const int* in_sizes, int n_in,
                              void* d_out, int out_size)
{
    const float* x      = (const float*)d_in[0];
    const float* rp     = (const float*)d_in[1];
    const float* w_qkv  = (const float*)d_in[2];
    const float* w_rel  = (const float*)d_in[3];
    const float* b_rel  = (const float*)d_in[4];
    const float* ln_g   = (const float*)d_in[5];
    const float* ln_b   = (const float*)d_in[6];
    const float* w_proj = (const float*)d_in[7];
    const float* b_proj = (const float*)d_in[8];
    float* out = (float*)d_out;

    cudaFuncSetAttribute(attn_kernel, cudaFuncAttributeMaxDynamicSharedMemorySize,
                         ATTN_SMEM_FLOATS * (int)sizeof(float));

    // K1: qkv projection + scatter to [b][h][l][d]
    gemm_kernel<<<dim3(16, 12), 256>>>(x, w_qkv, nullptr, nullptr, 0);
    // K2: rel bias (the hot kernel: 537 MB read, 2.1 GFLOP)
    rel_kernel<<<2048, 256>>>(rp, w_rel, b_rel, ln_g, ln_b);
    // K3: attention
    attn_kernel<<<dim3(16, 8, 2), 256, ATTN_SMEM_FLOATS * (int)sizeof(float)>>>();
    // K4: output projection + bias
    gemm_kernel<<<dim3(16, 4), 256>>>(nullptr, w_proj, b_proj, out, 1);
}

// round 2
// speedup vs baseline: 1.1660x; 1.1660x over previous
#include <cuda_runtime.h>
#include <math.h>

#define B_ 2
#define L_ 512
#define C_ 256
#define H_ 8
#define D_ 32
#define SCALE_ 0.17677669529663687f   // 1/sqrt(32)

typedef unsigned long long ull;

// ---------------- f32x2 packed-FMA helpers (sm_103a) ------------------------
__device__ __forceinline__ ull pack2(float a, float b) {
    ull r; asm("mov.b64 %0, {%1, %2};" : "=l"(r) : "f"(a), "f"(b)); return r;
}
__device__ __forceinline__ void unpack2(ull v, float& a, float& b) {
    asm("mov.b64 {%0, %1}, %2;" : "=f"(a), "=f"(b) : "l"(v));
}
__device__ __forceinline__ void ffma2(ull& d, ull a, ull b) {
    asm("fma.rn.f32x2 %0, %1, %2, %0;" : "+l"(d) : "l"(a), "l"(b));
}

// ------------------------- scratch (device globals) -------------------------
__device__ float g_q[B_*H_*L_*D_];          // 1 MB
__device__ float g_k[B_*H_*L_*D_];          // 1 MB
__device__ float g_v[B_*H_*L_*D_];          // 1 MB
__device__ float g_rel[B_*H_*L_*L_];        // 16 MB, [b][h][l][m]
__device__ float g_att[B_*L_*C_];           // 1 MB, [b][l][h*32+d]

// ===========================================================================
// GEMM: out[m][n] = sum_k A[m][k] * W[n][k]
// mode 0: A=x [1024][256], W=[768][256], scatter into g_q/g_k/g_v
// mode 1: A=g_att, W=[256][256], out += bias
// 64x32 tile, 128 threads, 4x4 micro via f32x2 (m-pairs).
// ===========================================================================
__global__ __launch_bounds__(128) void gemm_kernel(
    const float* __restrict__ A, const float* __restrict__ W,
    const float* __restrict__ bias, float* __restrict__ out, int mode)
{
    __shared__ __align__(16) float As[32][68];
    __shared__ __align__(16) float Ws[32][36];
    const float* Ap = (mode == 0) ? A : g_att;
    int tid  = threadIdx.x;
    int row0 = blockIdx.x * 64;
    int col0 = blockIdx.y * 32;
    int tx = tid & 7, ty = tid >> 3;

    ull acc2[2][4];
    #pragma unroll
    for (int i = 0; i < 2; i++)
        #pragma unroll
        for (int j = 0; j < 4; j++) acc2[i][j] = 0ull;

    for (int kc = 0; kc < 256; kc += 32) {
        #pragma unroll
        for (int i = 0; i < 4; i++) {                  // A: 2048 floats
            int idx = tid + i * 128;
            int r = idx >> 3, c4 = idx & 7;
            float4 av = *(const float4*)&Ap[(size_t)(row0 + r) * 256 + kc + c4 * 4];
            As[c4*4+0][r] = av.x; As[c4*4+1][r] = av.y;
            As[c4*4+2][r] = av.z; As[c4*4+3][r] = av.w;
        }
        #pragma unroll
        for (int i = 0; i < 2; i++) {                  // W: 1024 floats
            int idx = tid + i * 128;
            int r = idx >> 3, c4 = idx & 7;
            float4 wv = *(const float4*)&W[(size_t)(col0 + r) * 256 + kc + c4 * 4];
            Ws[c4*4+0][r] = wv.x; Ws[c4*4+1][r] = wv.y;
            Ws[c4*4+2][r] = wv.z; Ws[c4*4+3][r] = wv.w;
        }
        __syncthreads();
        #pragma unroll
        for (int kk = 0; kk < 32; kk++) {
            ulonglong2 a2 = *(const ulonglong2*)&As[kk][ty * 4];   // m-pairs
            float4 b4 = *(const float4*)&Ws[kk][tx * 4];
            ull bd[4] = { pack2(b4.x, b4.x), pack2(b4.y, b4.y),
                          pack2(b4.z, b4.z), pack2(b4.w, b4.w) };
            #pragma unroll
            for (int j = 0; j < 4; j++) {
                ffma2(acc2[0][j], a2.x, bd[j]);
                ffma2(acc2[1][j], a2.y, bd[j]);
            }
        }
        __syncthreads();
    }

    #pragma unroll
    for (int i2 = 0; i2 < 2; i2++) {
        #pragma unroll
        for (int j = 0; j < 4; j++) {
            float v0, v1;
            unpack2(acc2[i2][j], v0, v1);
            int n = col0 + tx * 4 + j;
            #pragma unroll
            for (int half = 0; half < 2; half++) {
                int m  = row0 + ty * 4 + i2 * 2 + half;
                float val = half ? v1 : v0;
                int bb = m >> 9, l = m & 511;
                if (mode == 0) {
                    int s = n >> 8, rem = n & 255, h = rem >> 5, d = rem & 31;
                    float* dst = (s == 0) ? g_q : (s == 1) ? g_k : g_v;
                    dst[(((size_t)bb * H_ + h) * L_ + l) * D_ + d] = val;
                } else {
                    out[(size_t)m * 256 + n] = val + bias[n];
                }
            }
        }
    }
}

// ===========================================================================
// rel bias: rel[b,h,l,m] = LN_h( gelu( rp[b,l,m,:] @ w_rel[h,:] + b_rel[h] ) )
// One thread per (b,l,m)-row. f32x2 over h-pairs. HBM-bound by design.
// ===========================================================================
__global__ __launch_bounds__(256) void rel_kernel(
    const float* __restrict__ rp, const float* __restrict__ w_rel,
    const float* __restrict__ b_rel, const float* __restrict__ ln_g,
    const float* __restrict__ ln_b)
{
    __shared__ __align__(16) float tile[256 * 36];
    __shared__ __align__(16) float ws[256 * 8];     // ws[c*8 + h]
    __shared__ float par[24];
    int tid = threadIdx.x;

    #pragma unroll
    for (int i = 0; i < 8; i++) {
        int idx = tid + i * 256;                     // idx = h*256 + c
        ws[(idx & 255) * 8 + (idx >> 8)] = w_rel[idx];
    }
    if (tid < 8) { par[tid] = b_rel[tid]; par[8 + tid] = ln_g[tid]; par[16 + tid] = ln_b[tid]; }

    ull acc2[4] = {0ull, 0ull, 0ull, 0ull};         // h pairs (0,1)(2,3)(4,5)(6,7)

    const float* rowp = rp + (size_t)blockIdx.x * (256 * 256);
    __syncthreads();

    for (int ch = 0; ch < 8; ch++) {
        #pragma unroll
        for (int i = 0; i < 8; i++) {
            int idx = tid + i * 256;
            int rr = idx >> 3, c4 = idx & 7;
            float4 v = *(const float4*)&rowp[(size_t)rr * 256 + ch * 32 + c4 * 4];
            *(float4*)&tile[rr * 36 + c4 * 4] = v;
        }
        __syncthreads();
        const float* trow = &tile[tid * 36];
        #pragma unroll
        for (int c = 0; c < 32; c += 4) {
            float4 r4 = *(const float4*)&trow[c];
            float rv[4] = {r4.x, r4.y, r4.z, r4.w};
            #pragma unroll
            for (int u = 0; u < 4; u++) {
                ull rd = pack2(rv[u], rv[u]);
                ulonglong2 w01 = *(const ulonglong2*)&ws[(ch * 32 + c + u) * 8];
                ulonglong2 w23 = *(const ulonglong2*)&ws[(ch * 32 + c + u) * 8 + 4];
                ffma2(acc2[0], rd, w01.x);
                ffma2(acc2[1], rd, w01.y);
                ffma2(acc2[2], rd, w23.x);
                ffma2(acc2[3], rd, w23.y);
            }
        }
        __syncthreads();
    }

    float acc[8];
    #pragma unroll
    for (int p = 0; p < 4; p++) unpack2(acc2[p], acc[2*p], acc[2*p+1]);

    float gv[8];
    float mu = 0.f;
    #pragma unroll
    for (int h = 0; h < 8; h++) {
        float xv = acc[h] + par[h];
        gv[h] = 0.5f * xv * (1.f + erff(xv * 0.7071067811865475f));
        mu += gv[h];
    }
    mu *= 0.125f;
    float var = 0.f;
    #pragma unroll
    for (int h = 0; h < 8; h++) { float d = gv[h] - mu; var += d * d; }
    var *= 0.125f;
    float rstd = rsqrtf(var + 1e-5f);

    size_t r  = (size_t)blockIdx.x * 256 + tid;
    int    m  = (int)(r & 511);
    size_t bl = r >> 9;
    int    bb = (int)(bl >> 9);
    int    l  = (int)(bl & 511);
    size_t base = (((size_t)bb * H_) * L_ + l) * (size_t)L_ + m;
    #pragma unroll
    for (int h = 0; h < 8; h++)
        g_rel[base + (size_t)h * (L_ * L_)] = (gv[h] - mu) * rstd * par[8 + h] + par[16 + h];
}

// ===========================================================================
// attention per (b, h, 32-l tile): f32x2 pass1 (d-pairs, k in packed regs),
// smem-staged v pass2 (d-pairs), __expf softmax.
// ===========================================================================
#define LPAD 516
#define ATTN_SMEM_FLOATS (32 * LPAD + 32 * 32 + 128 * 32 + 32)

__global__ __launch_bounds__(256) void attn_kernel()
{
    extern __shared__ __align__(16) float sm[];
    float* logits = sm;                         // [32][LPAD]
    float* q_s    = sm + 32 * LPAD;             // [32][32]
    float* v_s    = q_s + 32 * 32;              // [128][32]
    float* inv_s  = v_s + 128 * 32;             // [32]
    int tid = threadIdx.x;
    int b = blockIdx.z, h = blockIdx.y, l0 = blockIdx.x * 32;

    const float* qb   = g_q + (((size_t)(b * H_ + h)) * L_ + l0) * D_;
    const float* kb   = g_k + ((size_t)(b * H_ + h)) * L_ * D_;
    const float* vb   = g_v + ((size_t)(b * H_ + h)) * L_ * D_;
    const float* relb = g_rel + (((size_t)(b * H_ + h)) * L_ + l0) * L_;

    { int lq = tid >> 3, d4 = tid & 7;
      *(float4*)&q_s[lq * 32 + d4 * 4] = *(const float4*)&qb[lq * 32 + d4 * 4]; }

    // k rows m0, m1 held as packed d-pairs
    ull kp0[16], kp1[16];
    int m0 = tid, m1 = tid + 256;
    #pragma unroll
    for (int j = 0; j < 8; j++) {
        ulonglong2 t0 = *(const ulonglong2*)&kb[(size_t)m0 * 32 + j * 4];
        kp0[j*2] = t0.x; kp0[j*2+1] = t0.y;
        ulonglong2 t1 = *(const ulonglong2*)&kb[(size_t)m1 * 32 + j * 4];
        kp1[j*2] = t1.x; kp1[j*2+1] = t1.y;
    }
    __syncthreads();

    // pass 1: logits = (q.k + rel) * scale
    #pragma unroll 2
    for (int l = 0; l < 32; l++) {
        ull s0a = 0ull, s0b = 0ull, s1a = 0ull, s1b = 0ull;
        #pragma unroll
        for (int jj = 0; jj < 8; jj++) {
            ulonglong2 q2 = *(const ulonglong2*)&q_s[l * 32 + jj * 4];
            ffma2(s0a, q2.x, kp0[jj*2]);
            ffma2(s0b, q2.y, kp0[jj*2+1]);
            ffma2(s1a, q2.x, kp1[jj*2]);
            ffma2(s1b, q2.y, kp1[jj*2+1]);
        }
        float x0, y0, x1, y1, x2, y2, x3, y3;
        unpack2(s0a, x0, y0); unpack2(s0b, x1, y1);
        unpack2(s1a, x2, y2); unpack2(s1b, x3, y3);
        float s0 = (x0 + y0) + (x1 + y1);
        float s1 = (x2 + y2) + (x3 + y3);
        logits[l * LPAD + m0] = (s0 + relb[(size_t)l * L_ + m0]) * SCALE_;
        logits[l * LPAD + m1] = (s1 + relb[(size_t)l * L_ + m1]) * SCALE_;
    }
    __syncthreads();

    // softmax: warp per 4 rows
    int lane = tid & 31, wrp = tid >> 5;
    for (int lr = 0; lr < 4; lr++) {
        int l = wrp * 4 + lr;
        float* row = &logits[l * LPAD];
        float vals[16];
        float mx = -1e30f;
        #pragma unroll
        for (int j = 0; j < 16; j++) { vals[j] = row[lane + 32 * j]; mx = fmaxf(mx, vals[j]); }
        #pragma unroll
        for (int o = 16; o > 0; o >>= 1) mx = fmaxf(mx, __shfl_xor_sync(0xffffffff, mx, o));
        float sum = 0.f;
        #pragma unroll
        for (int j = 0; j < 16; j++) {
            float e = __expf(vals[j] - mx);
            row[lane + 32 * j] = e;
            sum += e;
        }
        #pragma unroll
        for (int o = 16; o > 0; o >>= 1) sum += __shfl_xor_sync(0xffffffff, sum, o);
        if (lane == 0) inv_s[l] = 1.f / sum;
    }

    // pass 2: out = p @ v, v staged in 128-row smem chunks
    int lo = tid >> 3, dq = tid & 7;
    ull a0 = 0ull, a1 = 0ull, a2 = 0ull, a3 = 0ull;
    for (int mc = 0; mc < 4; mc++) {
        __syncthreads();
        #pragma unroll
        for (int i = 0; i < 4; i++) {
            int idx = tid + i * 256;
            int r = idx >> 3, c4 = idx & 7;
            *(float4*)&v_s[r * 32 + c4 * 4] =
                *(const float4*)&vb[(size_t)(mc * 128 + r) * 32 + c4 * 4];
        }
        __syncthreads();
        const float* lrow = &logits[lo * LPAD + mc * 128];
        #pragma unroll 4
        for (int m4 = 0; m4 < 128; m4 += 4) {
            float4 p4 = *(const float4*)&lrow[m4];
            float pv[4] = {p4.x, p4.y, p4.z, p4.w};
            #pragma unroll
            for (int s = 0; s < 4; s++) {
                ull pd = pack2(pv[s], pv[s]);
                ulonglong2 vv = *(const ulonglong2*)&v_s[(m4 + s) * 32 + dq * 4];
                if (s & 1) { ffma2(a2, pd, vv.x); ffma2(a3, pd, vv.y); }
                else       { ffma2(a0, pd, vv.x); ffma2(a1, pd, vv.y); }
            }
        }
    }
    float ox0, ox1, oy0, oy1, oz0, oz1, ow0, ow1;
    unpack2(a0, ox0, oy0); unpack2(a2, ox1, oy1);
    unpack2(a1, oz0, ow0); unpack2(a3, oz1, ow1);
    float inv = inv_s[lo];
    float4 o;
    o.x = (ox0 + ox1) * inv; o.y = (oy0 + oy1) * inv;
    o.z = (oz0 + oz1) * inv; o.w = (ow0 + ow1) * inv;
    *(float4*)&g_att[((size_t)(b * L_) + l0 + lo) * C_ + h * D_ + dq * 4] = o;
}

// ===========================================================================
extern "C" void kernel_launch(void* const* d_in, const int* in_sizes, int n_in,
                              void* d_out, int out_size)
{
    const float* x      = (const float*)d_in[0];
    const float* rp     = (const float*)d_in[1];
    const float* w_qkv  = (const float*)d_in[2];
    const float* w_rel  = (const float*)d_in[3];
    const float* b_rel  = (const float*)d_in[4];
    const float* ln_g   = (const float*)d_in[5];
    const float* ln_b   = (const float*)d_in[6];
    const float* w_proj = (const float*)d_in[7];
    const float* b_proj = (const float*)d_in[8];
    float* out = (float*)d_out;

    cudaFuncSetAttribute(attn_kernel, cudaFuncAttributeMaxDynamicSharedMemorySize,
                         ATTN_SMEM_FLOATS * (int)sizeof(float));

    // K1: qkv projection (grid 384)
    gemm_kernel<<<dim3(16, 24), 128>>>(x, w_qkv, nullptr, nullptr, 0);
    // K2: rel bias — the HBM-bound hot kernel (537 MB read)
    rel_kernel<<<2048, 256>>>(rp, w_rel, b_rel, ln_g, ln_b);
    // K3: attention
    attn_kernel<<<dim3(16, 8, 2), 256, ATTN_SMEM_FLOATS * (int)sizeof(float)>>>();
    // K4: output projection + bias (grid 128)
    gemm_kernel<<<dim3(16, 8), 128>>>(nullptr, w_proj, b_proj, out, 1);
}